// round 16
// baseline (speedup 1.0000x reference)
#include <cuda_runtime.h>
#include <cuda_bf16.h>
#include <cstdint>

// ---------------------------------------------------------------------------
// cosFormer linear attention — bf16x3 split tensor-core GEMMs.
// proj: fused Q/K/V launch, 4-buffer smem, sync every 2 K-chunks (R13).
// kv:   cp.async 3-stage BK=32 (measured 290us, tensor 58%, 2 CTA/SM).
// attn: dual GEMM (Q@KVs, Q@KVc), N=64, 2-stage double buffer (R13-passing).
// z:    warp-per-row (R15). ksum: hi-only.
// ---------------------------------------------------------------------------

#define L_DIM 2048
#define S_DIM 2048
#define B_DIM 4
#define E_DIM 1024
#define D2    (2 * E_DIM)
#define EPS_F 1e-6f
#define PIO2  1.5707963267948966f
#define INV_M (1.0f / 2048.0f)
#define NCHUNK 16
#define NELEM ((size_t)B_DIM * L_DIM * E_DIM)

typedef __nv_bfloat16 bf16;
typedef __nv_bfloat162 bf162;

// ---------------- scratch ---------------------------------------------------
__device__ bf16 g_Qh[NELEM],  g_Ql[NELEM];
__device__ bf16 g_KSh[NELEM], g_KSl[NELEM], g_KCh[NELEM], g_KCl[NELEM];
__device__ bf16 g_Vh[NELEM],  g_Vl[NELEM];
__device__ bf16 g_KVh[NELEM], g_KVl[NELEM];   // [b][d(0..2E)][m]
__device__ float g_KsumPartS[NCHUNK * B_DIM * E_DIM];
__device__ float g_KsumPartC[NCHUNK * B_DIM * E_DIM];
__device__ float g_KsumS[B_DIM * E_DIM];
__device__ float g_KsumC[B_DIM * E_DIM];
__device__ float g_Z[B_DIM * L_DIM];

// ---------------- asm helpers ----------------------------------------------
__device__ __forceinline__ uint32_t sptr(const void* p) {
    return (uint32_t)__cvta_generic_to_shared(p);
}
__device__ __forceinline__ void cp16(uint32_t dst, const void* src) {
    asm volatile("cp.async.cg.shared.global [%0], [%1], 16;" :: "r"(dst), "l"(src));
}
#define CP_COMMIT asm volatile("cp.async.commit_group;")
#define CP_WAIT1  asm volatile("cp.async.wait_group 1;")
#define CP_WAIT0  asm volatile("cp.async.wait_group 0;")

__device__ __forceinline__ void ldm_x4(uint32_t* r, uint32_t a) {
    asm volatile("ldmatrix.sync.aligned.m8n8.x4.shared.b16 {%0,%1,%2,%3}, [%4];"
                 : "=r"(r[0]), "=r"(r[1]), "=r"(r[2]), "=r"(r[3]) : "r"(a));
}
__device__ __forceinline__ void ldm_x4t(uint32_t* r, uint32_t a) {
    asm volatile("ldmatrix.sync.aligned.m8n8.x4.trans.shared.b16 {%0,%1,%2,%3}, [%4];"
                 : "=r"(r[0]), "=r"(r[1]), "=r"(r[2]), "=r"(r[3]) : "r"(a));
}
__device__ __forceinline__ void ldm_x2(uint32_t* r, uint32_t a) {
    asm volatile("ldmatrix.sync.aligned.m8n8.x2.shared.b16 {%0,%1}, [%2];"
                 : "=r"(r[0]), "=r"(r[1]) : "r"(a));
}
__device__ __forceinline__ void ldm_x2t(uint32_t* r, uint32_t a) {
    asm volatile("ldmatrix.sync.aligned.m8n8.x2.trans.shared.b16 {%0,%1}, [%2];"
                 : "=r"(r[0]), "=r"(r[1]) : "r"(a));
}
__device__ __forceinline__ void mma16816(float* c, const uint32_t* a, const uint32_t* b) {
    asm volatile(
        "mma.sync.aligned.m16n8k16.row.col.f32.bf16.bf16.f32 "
        "{%0,%1,%2,%3}, {%4,%5,%6,%7}, {%8,%9}, {%0,%1,%2,%3};"
        : "+f"(c[0]), "+f"(c[1]), "+f"(c[2]), "+f"(c[3])
        : "r"(a[0]), "r"(a[1]), "r"(a[2]), "r"(a[3]), "r"(b[0]), "r"(b[1]));
}
__device__ __forceinline__ void split_bf16(float x, bf16& h, bf16& l) {
    h = __float2bfloat16(x);
    l = __float2bfloat16(x - __bfloat162float(h));
}
__device__ __forceinline__ bf162 split2(float a, float b, bf16* lo) {
    bf16 h0, l0, h1, l1;
    split_bf16(a, h0, l0); split_bf16(b, h1, l1);
    lo[0] = l0; lo[1] = l1;
    return __halves2bfloat162(h0, h1);
}

#define MMA_BLOCK(AH, BH) \
    _Pragma("unroll") for (int mi = 0; mi < 4; mi++) \
    _Pragma("unroll") for (int ni = 0; ni < 4; ni++) mma16816(cacc[mi][ni], AH[mi], BH[ni]);

// ---------------------------------------------------------------------------
// proj (fused Q/K/V via blockIdx.z): C = X·W^T + bias.
// 4-buffer smem pipeline, __syncthreads every 2 K-chunks.
// ---------------------------------------------------------------------------
#define PJ_BUFE 3072
#define PJ_NBUF 4
#define PJ_ARRE (PJ_NBUF * PJ_BUFE)
#define PJ_SMEM (4 * PJ_ARRE * 2)
__global__ __launch_bounds__(256, 2) void proj_mma(
    const float* __restrict__ query, const float* __restrict__ key,
    const float* __restrict__ value,
    const float* __restrict__ Wq, const float* __restrict__ Wk,
    const float* __restrict__ Wv,
    const float* __restrict__ bq, const float* __restrict__ bk,
    const float* __restrict__ bv,
    bf16* __restrict__ Qh, bf16* __restrict__ Ql,
    bf16* __restrict__ KSh, bf16* __restrict__ KSl,
    bf16* __restrict__ KCh, bf16* __restrict__ KCl,
    bf16* __restrict__ Vh, bf16* __restrict__ Vl)
{
    extern __shared__ bf16 sm[];
    bf16* Ah = sm;
    bf16* Al = sm + PJ_ARRE;
    bf16* Bh = sm + 2 * PJ_ARRE;
    bf16* Bl = sm + 3 * PJ_ARRE;

    const int zz = blockIdx.z;
    const float *X, *W, *bias;
    bf16 *o0h, *o0l, *o1h = nullptr, *o1l = nullptr;
    int mode, do_relu;
    if (zz == 0)      { X = query; W = Wq; bias = bq; o0h = Qh;  o0l = Ql;  mode = 0; do_relu = 1; }
    else if (zz == 1) { X = key;   W = Wk; bias = bk; o0h = KSh; o0l = KSl; o1h = KCh; o1l = KCl; mode = 1; do_relu = 1; }
    else              { X = value; W = Wv; bias = bv; o0h = Vh;  o0l = Vl;  mode = 0; do_relu = 0; }

    const int tid = threadIdx.x, lane = tid & 31, warp = tid >> 5;
    const int wy = warp >> 2, wx = warp & 3;
    const int m0 = blockIdx.y * 128, n0 = blockIdx.x * 128;
    const int lr = tid >> 2, lc = tid & 3;

    uint32_t aA[4], aB[4];
    {
        int ar = lane & 15, ac = (lane >> 4) << 3;
#pragma unroll
        for (int mi = 0; mi < 4; mi++)
            aA[mi] = sptr(&Ah[(wy * 64 + mi * 16 + ar) * 24 + ac]);
        int br = lane & 7, bc = ((lane >> 3) & 1) << 3;
#pragma unroll
        for (int ni = 0; ni < 4; ni++)
            aB[ni] = sptr(&Bh[(wx * 32 + ni * 8 + br) * 24 + bc]);
    }
    const uint32_t dHL = (uint32_t)PJ_ARRE * 2;
    const uint32_t dBUF = (uint32_t)PJ_BUFE * 2;

    float4 xa[2], wb[2];
    auto gload = [&](int k0) {
#pragma unroll
        for (int it = 0; it < 2; it++) {
            xa[it] = *(const float4*)&X[(size_t)(m0 + lr + it * 64) * E_DIM + k0 + lc * 4];
            wb[it] = *(const float4*)&W[(size_t)(n0 + lr + it * 64) * E_DIM + k0 + lc * 4];
        }
    };
    auto sstore = [&](int buf) {
#pragma unroll
        for (int it = 0; it < 2; it++) {
            int row = lr + it * 64;
            int off = buf * PJ_BUFE + row * 24 + lc * 4;
            bf16 lo[2];
            bf162 hh = split2(xa[it].x, xa[it].y, lo);
            *(bf162*)&Ah[off]     = hh; *(bf162*)&Al[off]     = __halves2bfloat162(lo[0], lo[1]);
            hh = split2(xa[it].z, xa[it].w, lo);
            *(bf162*)&Ah[off + 2] = hh; *(bf162*)&Al[off + 2] = __halves2bfloat162(lo[0], lo[1]);
            hh = split2(wb[it].x, wb[it].y, lo);
            *(bf162*)&Bh[off]     = hh; *(bf162*)&Bl[off]     = __halves2bfloat162(lo[0], lo[1]);
            hh = split2(wb[it].z, wb[it].w, lo);
            *(bf162*)&Bh[off + 2] = hh; *(bf162*)&Bl[off + 2] = __halves2bfloat162(lo[0], lo[1]);
        }
    };

    float cacc[4][4][4];
#pragma unroll
    for (int i = 0; i < 4; i++)
#pragma unroll
        for (int j = 0; j < 4; j++)
#pragma unroll
            for (int k = 0; k < 4; k++) cacc[i][j][k] = 0.f;

    const int NIT = E_DIM / 16;
    gload(0);  sstore(0);
    gload(16); sstore(1);
    gload(32);
    __syncthreads();
    for (int i = 0; i < NIT; i++) {
        if (i + 2 < NIT) {
            sstore((i + 2) & 3);
            if (i + 3 < NIT) gload((i + 3) * 16);
        }
        uint32_t bo = (i & 3) * dBUF;
        uint32_t ah[4][4], al[4][4], bh[4][2], bl[4][2];
#pragma unroll
        for (int mi = 0; mi < 4; mi++) { ldm_x4(ah[mi], aA[mi] + bo); ldm_x4(al[mi], aA[mi] + bo + dHL); }
#pragma unroll
        for (int ni = 0; ni < 4; ni++) { ldm_x2(bh[ni], aB[ni] + bo); ldm_x2(bl[ni], aB[ni] + bo + dHL); }
        MMA_BLOCK(ah, bh); MMA_BLOCK(ah, bl); MMA_BLOCK(al, bh);
        if (i & 1) __syncthreads();
    }

    const int gid = lane >> 2, tig = lane & 3;
#pragma unroll
    for (int mi = 0; mi < 4; mi++)
#pragma unroll
        for (int ni = 0; ni < 4; ni++) {
            int col = n0 + wx * 32 + ni * 8 + tig * 2;
            float b0v = bias[col], b1v = bias[col + 1];
#pragma unroll
            for (int half = 0; half < 2; half++) {
                int m = m0 + wy * 64 + mi * 16 + gid + half * 8;
                int bb = m & (B_DIM - 1);
                int t = m >> 2;
                float c0 = cacc[mi][ni][half * 2] + b0v;
                float c1 = cacc[mi][ni][half * 2 + 1] + b1v;
                if (do_relu) { c0 = fmaxf(c0, 0.f); c1 = fmaxf(c1, 0.f); }
                size_t o = ((size_t)bb * L_DIM + t) * E_DIM + col;
                bf16 lo[2];
                if (mode == 1) {
                    float th = PIO2 * (float)(t + 1) * INV_M;
                    float sn = __sinf(th), cs = __cosf(th);
                    bf162 hh = split2(sn * c0, sn * c1, lo);
                    *(bf162*)&o0h[o] = hh; *(bf162*)&o0l[o] = __halves2bfloat162(lo[0], lo[1]);
                    hh = split2(cs * c0, cs * c1, lo);
                    *(bf162*)&o1h[o] = hh; *(bf162*)&o1l[o] = __halves2bfloat162(lo[0], lo[1]);
                } else {
                    bf162 hh = split2(c0, c1, lo);
                    *(bf162*)&o0h[o] = hh; *(bf162*)&o0l[o] = __halves2bfloat162(lo[0], lo[1]);
                }
            }
        }
}

// ---------------------------------------------------------------------------
// kv: KV[b,d,m] = sum_s ksel[b,s,d] * v[b,s,m]. cp.async 3-stage, BK=32.
// ---------------------------------------------------------------------------
#define K_STAGE 34816
#define K_SMEM  (3 * K_STAGE)
__global__ __launch_bounds__(256) void kv_mma(
    const bf16* __restrict__ ksh, const bf16* __restrict__ ksl,
    const bf16* __restrict__ kch, const bf16* __restrict__ kcl,
    const bf16* __restrict__ vh,  const bf16* __restrict__ vl,
    bf16* __restrict__ kvh, bf16* __restrict__ kvl)
{
    extern __shared__ bf16 sm[];
    const int tid = threadIdx.x, lane = tid & 31, warp = tid >> 5;
    const int wy = warp >> 2, wx = warp & 3;
    const int b = blockIdx.z, d0 = blockIdx.y * 128, m0 = blockIdx.x * 128;
    const uint32_t smb = sptr(sm);

    const bf16 *Ahg, *Alg;
    int dbase;
    if (d0 < E_DIM) { Ahg = ksh; Alg = ksl; dbase = d0; }
    else            { Ahg = kch; Alg = kcl; dbase = d0 - E_DIM; }
    Ahg += (size_t)b * S_DIM * E_DIM; Alg += (size_t)b * S_DIM * E_DIM;
    const bf16* Vhg = vh + (size_t)b * S_DIM * E_DIM;
    const bf16* Vlg = vl + (size_t)b * S_DIM * E_DIM;

    uint32_t aA[4], aB[4];
    {
        int ar = (lane & 7) + ((lane >> 4) << 3);
        int ac = ((lane >> 3) & 1) << 3;
#pragma unroll
        for (int mi = 0; mi < 4; mi++)
            aA[mi] = smb + (ar * 136 + wy * 64 + mi * 16 + ac) * 2;
        int br = lane & 15;
#pragma unroll
        for (int ni = 0; ni < 4; ni++)
            aB[ni] = smb + 17408 + (br * 136 + wx * 32 + ni * 8) * 2;
    }

    auto load_stage = [&](int st, int s0) {
        uint32_t base = smb + st * K_STAGE;
#pragma unroll
        for (int u = 0; u < 2; u++) {
            int id = tid + u * 256;
            int row = id >> 4, seg = id & 15;
            uint32_t da = base + (row * 136 + seg * 8) * 2;
            size_t ga = (size_t)(s0 + row) * E_DIM + dbase + seg * 8;
            cp16(da, Ahg + ga); cp16(da + 8704, Alg + ga);
            size_t gb = (size_t)(s0 + row) * E_DIM + m0 + seg * 8;
            cp16(da + 17408, Vhg + gb); cp16(da + 26112, Vlg + gb);
        }
    };

    float cacc[4][4][4];
#pragma unroll
    for (int i = 0; i < 4; i++)
#pragma unroll
        for (int j = 0; j < 4; j++)
#pragma unroll
            for (int k = 0; k < 4; k++) cacc[i][j][k] = 0.f;

    load_stage(0, 0);  CP_COMMIT;
    load_stage(1, 32); CP_COMMIT;
    int buf = 0;
    for (int s0 = 0; s0 < S_DIM; s0 += 32) {
        CP_WAIT1; __syncthreads();
        if (s0 + 64 < S_DIM) {
            int nst = buf + 2; if (nst >= 3) nst -= 3;
            load_stage(nst, s0 + 64);
        }
        CP_COMMIT;
        uint32_t soff = buf * K_STAGE;
#pragma unroll
        for (int kk = 0; kk < 32; kk += 16) {
            uint32_t ko = soff + kk * 272;
            uint32_t ah[4][4], al[4][4], bh[4][2], bl[4][2];
#pragma unroll
            for (int mi = 0; mi < 4; mi++) { ldm_x4t(ah[mi], aA[mi] + ko); ldm_x4t(al[mi], aA[mi] + ko + 8704); }
#pragma unroll
            for (int ni = 0; ni < 4; ni++) { ldm_x2t(bh[ni], aB[ni] + ko); ldm_x2t(bl[ni], aB[ni] + ko + 8704); }
            MMA_BLOCK(ah, bh); MMA_BLOCK(ah, bl); MMA_BLOCK(al, bh);
        }
        buf++; if (buf == 3) buf = 0;
    }

    const int gid = lane >> 2, tig = lane & 3;
#pragma unroll
    for (int mi = 0; mi < 4; mi++)
#pragma unroll
        for (int ni = 0; ni < 4; ni++) {
            int col = m0 + wx * 32 + ni * 8 + tig * 2;
#pragma unroll
            for (int half = 0; half < 2; half++) {
                int d = d0 + wy * 64 + mi * 16 + gid + half * 8;
                size_t o = ((size_t)b * D2 + d) * E_DIM + col;
                bf16 lo[2];
                bf162 hh = split2(cacc[mi][ni][half * 2], cacc[mi][ni][half * 2 + 1], lo);
                *(bf162*)&kvh[o] = hh;
                *(bf162*)&kvl[o] = __halves2bfloat162(lo[0], lo[1]);
            }
        }
}

// ---------------------------------------------------------------------------
// attn (dual): Y1 = Q@KVs, Y2 = Q@KVc; out = Z·(sin_l·Y1 + cos_l·Y2).
// Tile M=128 N=64 BK=32; warps 2x4; 2-stage double buffer, 2 CTAs/SM.
// (R13-passing version, byte-identical.)
// Stage bytes: Ah 0, Al 10240, B1h 20480, B1l 25088, B2h 29696, B2l 34304.
// ---------------------------------------------------------------------------
#define AT_STAGEE 19456
#define AT_STAGE  (AT_STAGEE * 2)
#define AT_SMEM   (2 * AT_STAGE)
__global__ __launch_bounds__(256, 2) void attn_dual(
    const bf16* __restrict__ qh, const bf16* __restrict__ ql,
    const bf16* __restrict__ kvh, const bf16* __restrict__ kvl,
    float* __restrict__ out)
{
    extern __shared__ bf16 sm[];
    const int tid = threadIdx.x, lane = tid & 31, warp = tid >> 5;
    const int wy = warp >> 2, wx = warp & 3;   // wy 0..1, wx 0..3
    const int b = blockIdx.z, l0 = blockIdx.y * 128, m0 = blockIdx.x * 64;
    const uint32_t smb = sptr(sm);

    const bf16* Qh = qh + (size_t)b * L_DIM * E_DIM;
    const bf16* Ql = ql + (size_t)b * L_DIM * E_DIM;
    const bf16* KVh = kvh + (size_t)b * D2 * E_DIM;
    const bf16* KVl = kvl + (size_t)b * D2 * E_DIM;

    uint32_t aA[4], aB[2];
    {
        int ar = lane & 15, ac = (lane >> 4) << 3;
#pragma unroll
        for (int mi = 0; mi < 4; mi++)
            aA[mi] = smb + ((wy * 64 + mi * 16 + ar) * 40 + ac) * 2;
        int br = lane & 15;
#pragma unroll
        for (int ni = 0; ni < 2; ni++)
            aB[ni] = smb + (10240 + (br * 72 + wx * 16 + ni * 8)) * 2;
    }

    auto load_stage = [&](int st, int k0) {
        uint32_t base = smb + st * AT_STAGE;
        // A: 128x32 hi/lo
#pragma unroll
        for (int u = 0; u < 2; u++) {
            int id = tid + u * 256;
            int row = id >> 2, seg = id & 3;
            uint32_t da = base + (row * 40 + seg * 8) * 2;
            size_t ga = (size_t)(l0 + row) * E_DIM + k0 + seg * 8;
            cp16(da, Qh + ga); cp16(da + 10240, Ql + ga);
        }
        // B1 (KVs rows k0..), B2 (KVc rows E+k0..): each 32x64 hi/lo
        {
            int row = tid >> 3, seg = tid & 7;
            uint32_t db = base + 20480 + (row * 72 + seg * 8) * 2;
            size_t g1 = (size_t)(k0 + row) * E_DIM + m0 + seg * 8;
            size_t g2 = (size_t)(E_DIM + k0 + row) * E_DIM + m0 + seg * 8;
            cp16(db, KVh + g1);         cp16(db + 4608, KVl + g1);
            cp16(db + 9216, KVh + g2);  cp16(db + 13824, KVl + g2);
        }
    };

    float cacc[2][4][2][4];
#pragma unroll
    for (int s = 0; s < 2; s++)
#pragma unroll
        for (int i = 0; i < 4; i++)
#pragma unroll
            for (int j = 0; j < 2; j++)
#pragma unroll
                for (int k = 0; k < 4; k++) cacc[s][i][j][k] = 0.f;

    // 2-stage double buffer: wait-all, sync, prefetch other buffer, consume.
    load_stage(0, 0); CP_COMMIT;
    int buf = 0;
    for (int k0 = 0; k0 < E_DIM; k0 += 32) {
        CP_WAIT0; __syncthreads();
        if (k0 + 32 < E_DIM) load_stage(buf ^ 1, k0 + 32);
        CP_COMMIT;
        uint32_t soff = buf * AT_STAGE;
#pragma unroll
        for (int kk = 0; kk < 32; kk += 16) {
            uint32_t koA = soff + kk * 2;
            uint32_t koB = soff + kk * 144;   // 72 elems * 2B per row
            uint32_t ah[4][4], al[4][4];
#pragma unroll
            for (int mi = 0; mi < 4; mi++) { ldm_x4(ah[mi], aA[mi] + koA); ldm_x4(al[mi], aA[mi] + koA + 10240); }
#pragma unroll
            for (int mat = 0; mat < 2; mat++) {
                uint32_t mo = koB + mat * 9216;
                uint32_t bh[2][2], bl[2][2];
#pragma unroll
                for (int ni = 0; ni < 2; ni++) { ldm_x2t(bh[ni], aB[ni] + mo); ldm_x2t(bl[ni], aB[ni] + mo + 4608); }
#pragma unroll
                for (int mi = 0; mi < 4; mi++)
#pragma unroll
                    for (int ni = 0; ni < 2; ni++) {
                        mma16816(cacc[mat][mi][ni], ah[mi], bh[ni]);
                        mma16816(cacc[mat][mi][ni], ah[mi], bl[ni]);
                        mma16816(cacc[mat][mi][ni], al[mi], bh[ni]);
                    }
            }
        }
        buf ^= 1;
    }

    const int gid = lane >> 2, tig = lane & 3;
#pragma unroll
    for (int mi = 0; mi < 4; mi++)
#pragma unroll
        for (int half = 0; half < 2; half++) {
            int l = l0 + wy * 64 + mi * 16 + gid + half * 8;
            float th = PIO2 * (float)(l + 1) * INV_M;
            float sn = __sinf(th), cs = __cosf(th);
            float zv = g_Z[b * L_DIM + l];
#pragma unroll
            for (int ni = 0; ni < 2; ni++) {
                int col = m0 + wx * 16 + ni * 8 + tig * 2;
                float v0 = zv * (sn * cacc[0][mi][ni][half * 2]     + cs * cacc[1][mi][ni][half * 2]);
                float v1 = zv * (sn * cacc[0][mi][ni][half * 2 + 1] + cs * cacc[1][mi][ni][half * 2 + 1]);
                *(float2*)&out[((size_t)l * B_DIM + b) * E_DIM + col] = make_float2(v0, v1);
            }
        }
}

// ---------------------------------------------------------------------------
// ksum (hi-only) + z (warp-per-row)
// ---------------------------------------------------------------------------
__global__ void ksum_part_kernel()
{
    const int f = blockIdx.x * 256 + threadIdx.x;
    const int b = blockIdx.y;
    const int chunk = blockIdx.z;
    const int s0 = chunk * (S_DIM / NCHUNK);
    float ss = 0.f, sc = 0.f;
#pragma unroll 4
    for (int i = 0; i < S_DIM / NCHUNK; i++) {
        size_t idx = ((size_t)b * S_DIM + s0 + i) * E_DIM + f;
        ss += __bfloat162float(g_KSh[idx]);
        sc += __bfloat162float(g_KCh[idx]);
    }
    g_KsumPartS[(chunk * B_DIM + b) * E_DIM + f] = ss;
    g_KsumPartC[(chunk * B_DIM + b) * E_DIM + f] = sc;
}

__global__ void ksum_reduce_kernel()
{
    int idx = blockIdx.x * 256 + threadIdx.x;
    if (idx >= B_DIM * E_DIM) return;
    float ss = 0.f, sc = 0.f;
#pragma unroll
    for (int c = 0; c < NCHUNK; c++) {
        ss += g_KsumPartS[c * B_DIM * E_DIM + idx];
        sc += g_KsumPartC[c * B_DIM * E_DIM + idx];
    }
    g_KsumS[idx] = ss;
    g_KsumC[idx] = sc;
}

__global__ void z_kernel()
{
    const int warp = threadIdx.x >> 5, lane = threadIdx.x & 31;
    const int l = blockIdx.x * 8 + warp;
    const int b = blockIdx.y;
    const size_t base = ((size_t)b * L_DIM + l) * E_DIM;
    const float th = PIO2 * (float)(l + 1) * INV_M;
    const float sl = __sinf(th), cl = __cosf(th);

    float acc = 0.f;
#pragma unroll 8
    for (int jj = 0; jj < 32; jj++) {
        int f = jj * 32 + lane;
        float q = __bfloat162float(g_Qh[base + f]);
        acc += q * (sl * g_KsumS[b * E_DIM + f] + cl * g_KsumC[b * E_DIM + f]);
    }
#pragma unroll
    for (int off = 16; off > 0; off >>= 1)
        acc += __shfl_down_sync(0xFFFFFFFFu, acc, off);
    if (lane == 0)
        g_Z[b * L_DIM + l] = 1.f / fmaxf(acc, EPS_F);
}

// ---------------------------------------------------------------------------
// Launch
// ---------------------------------------------------------------------------
extern "C" void kernel_launch(void* const* d_in, const int* in_sizes, int n_in,
                              void* d_out, int out_size)
{
    const float* query = (const float*)d_in[0];
    const float* key   = (const float*)d_in[1];
    const float* value = (const float*)d_in[2];
    const float* Wq    = (const float*)d_in[3];
    const float* bq    = (const float*)d_in[4];
    const float* Wk    = (const float*)d_in[5];
    const float* bk    = (const float*)d_in[6];
    const float* Wv    = (const float*)d_in[7];
    const float* bv    = (const float*)d_in[8];
    float* out = (float*)d_out;

    cudaFuncSetAttribute(proj_mma,  cudaFuncAttributeMaxDynamicSharedMemorySize, PJ_SMEM);
    cudaFuncSetAttribute(kv_mma,    cudaFuncAttributeMaxDynamicSharedMemorySize, K_SMEM);
    cudaFuncSetAttribute(attn_dual, cudaFuncAttributeMaxDynamicSharedMemorySize, AT_SMEM);

    bf16 *Qh, *Ql, *KSh, *KSl, *KCh, *KCl, *Vh, *Vl, *KVh, *KVl;
    cudaGetSymbolAddress((void**)&Qh, g_Qh);   cudaGetSymbolAddress((void**)&Ql, g_Ql);
    cudaGetSymbolAddress((void**)&KSh, g_KSh); cudaGetSymbolAddress((void**)&KSl, g_KSl);
    cudaGetSymbolAddress((void**)&KCh, g_KCh); cudaGetSymbolAddress((void**)&KCl, g_KCl);
    cudaGetSymbolAddress((void**)&Vh, g_Vh);   cudaGetSymbolAddress((void**)&Vl, g_Vl);
    cudaGetSymbolAddress((void**)&KVh, g_KVh); cudaGetSymbolAddress((void**)&KVl, g_KVl);

    dim3 gProj(E_DIM / 128, (L_DIM * B_DIM) / 128, 3);   // (8, 64, 3) fused Q/K/V
    proj_mma<<<gProj, 256, PJ_SMEM>>>(query, key, value, Wq, Wk, Wv, bq, bk, bv,
                                      Qh, Ql, KSh, KSl, KCh, KCl, Vh, Vl);

    dim3 gKV(E_DIM / 128, D2 / 128, B_DIM);           // (8, 16, 4)
    kv_mma<<<gKV, 256, K_SMEM>>>(KSh, KSl, KCh, KCl, Vh, Vl, KVh, KVl);

    dim3 gKsum(E_DIM / 256, B_DIM, NCHUNK);
    ksum_part_kernel<<<gKsum, 256>>>();
    ksum_reduce_kernel<<<(B_DIM * E_DIM + 255) / 256, 256>>>();
    dim3 gZ(L_DIM / 8, B_DIM);
    z_kernel<<<gZ, 256>>>();

    dim3 gAttn(E_DIM / 64, L_DIM / 128, B_DIM);       // (16, 16, 4)
    attn_dual<<<gAttn, 256, AT_SMEM>>>(Qh, Ql, KVh, KVl, out);
}

// round 17
// speedup vs baseline: 1.0027x; 1.0027x over previous
#include <cuda_runtime.h>
#include <cuda_bf16.h>
#include <cstdint>

// ---------------------------------------------------------------------------
// cosFormer linear attention — bf16x3 split tensor-core GEMMs.
// R16: weights pre-split ONCE (12MB prepass); proj W-path loads bf16 uint2
//      (split math + half W traffic removed from the 64x-replayed mainloop).
// proj: fused Q/K/V launch, 4-buffer smem, sync every 2 K-chunks.
// kv:   cp.async 3-stage BK=32 (measured 290us, tensor 58%, 2 CTA/SM).
// attn: dual GEMM (Q@KVs, Q@KVc), N=64, 2-stage double buffer.
// z: warp-per-row. ksum: hi-only.
// ---------------------------------------------------------------------------

#define L_DIM 2048
#define S_DIM 2048
#define B_DIM 4
#define E_DIM 1024
#define D2    (2 * E_DIM)
#define EE    (E_DIM * E_DIM)
#define EPS_F 1e-6f
#define PIO2  1.5707963267948966f
#define INV_M (1.0f / 2048.0f)
#define NCHUNK 16
#define NELEM ((size_t)B_DIM * L_DIM * E_DIM)

typedef __nv_bfloat16 bf16;
typedef __nv_bfloat162 bf162;

// ---------------- scratch ---------------------------------------------------
__device__ bf16 g_Qh[NELEM],  g_Ql[NELEM];
__device__ bf16 g_KSh[NELEM], g_KSl[NELEM], g_KCh[NELEM], g_KCl[NELEM];
__device__ bf16 g_Vh[NELEM],  g_Vl[NELEM];
__device__ bf16 g_KVh[NELEM], g_KVl[NELEM];   // [b][d(0..2E)][m]
__device__ bf16 g_Wh[3 * EE], g_Wl[3 * EE];   // pre-split weights (Wq,Wk,Wv)
__device__ float g_KsumPartS[NCHUNK * B_DIM * E_DIM];
__device__ float g_KsumPartC[NCHUNK * B_DIM * E_DIM];
__device__ float g_KsumS[B_DIM * E_DIM];
__device__ float g_KsumC[B_DIM * E_DIM];
__device__ float g_Z[B_DIM * L_DIM];

// ---------------- asm helpers ----------------------------------------------
__device__ __forceinline__ uint32_t sptr(const void* p) {
    return (uint32_t)__cvta_generic_to_shared(p);
}
__device__ __forceinline__ void cp16(uint32_t dst, const void* src) {
    asm volatile("cp.async.cg.shared.global [%0], [%1], 16;" :: "r"(dst), "l"(src));
}
#define CP_COMMIT asm volatile("cp.async.commit_group;")
#define CP_WAIT1  asm volatile("cp.async.wait_group 1;")
#define CP_WAIT0  asm volatile("cp.async.wait_group 0;")

__device__ __forceinline__ void ldm_x4(uint32_t* r, uint32_t a) {
    asm volatile("ldmatrix.sync.aligned.m8n8.x4.shared.b16 {%0,%1,%2,%3}, [%4];"
                 : "=r"(r[0]), "=r"(r[1]), "=r"(r[2]), "=r"(r[3]) : "r"(a));
}
__device__ __forceinline__ void ldm_x4t(uint32_t* r, uint32_t a) {
    asm volatile("ldmatrix.sync.aligned.m8n8.x4.trans.shared.b16 {%0,%1,%2,%3}, [%4];"
                 : "=r"(r[0]), "=r"(r[1]), "=r"(r[2]), "=r"(r[3]) : "r"(a));
}
__device__ __forceinline__ void ldm_x2(uint32_t* r, uint32_t a) {
    asm volatile("ldmatrix.sync.aligned.m8n8.x2.shared.b16 {%0,%1}, [%2];"
                 : "=r"(r[0]), "=r"(r[1]) : "r"(a));
}
__device__ __forceinline__ void ldm_x2t(uint32_t* r, uint32_t a) {
    asm volatile("ldmatrix.sync.aligned.m8n8.x2.trans.shared.b16 {%0,%1}, [%2];"
                 : "=r"(r[0]), "=r"(r[1]) : "r"(a));
}
__device__ __forceinline__ void mma16816(float* c, const uint32_t* a, const uint32_t* b) {
    asm volatile(
        "mma.sync.aligned.m16n8k16.row.col.f32.bf16.bf16.f32 "
        "{%0,%1,%2,%3}, {%4,%5,%6,%7}, {%8,%9}, {%0,%1,%2,%3};"
        : "+f"(c[0]), "+f"(c[1]), "+f"(c[2]), "+f"(c[3])
        : "r"(a[0]), "r"(a[1]), "r"(a[2]), "r"(a[3]), "r"(b[0]), "r"(b[1]));
}
__device__ __forceinline__ void split_bf16(float x, bf16& h, bf16& l) {
    h = __float2bfloat16(x);
    l = __float2bfloat16(x - __bfloat162float(h));
}
__device__ __forceinline__ bf162 split2(float a, float b, bf16* lo) {
    bf16 h0, l0, h1, l1;
    split_bf16(a, h0, l0); split_bf16(b, h1, l1);
    lo[0] = l0; lo[1] = l1;
    return __halves2bfloat162(h0, h1);
}

#define MMA_BLOCK(AH, BH) \
    _Pragma("unroll") for (int mi = 0; mi < 4; mi++) \
    _Pragma("unroll") for (int ni = 0; ni < 4; ni++) mma16816(cacc[mi][ni], AH[mi], BH[ni]);

// ---------------------------------------------------------------------------
// weight split prepass (R3-proven logic)
// ---------------------------------------------------------------------------
__global__ void split_w_kernel(const float4* __restrict__ src,
                               bf162* __restrict__ h, bf162* __restrict__ l, int n4)
{
    int i = blockIdx.x * 256 + threadIdx.x;
    if (i >= n4) return;
    float4 v = src[i];
    bf16 lo[2];
    bf162 hh = split2(v.x, v.y, lo);
    h[i * 2] = hh; l[i * 2] = __halves2bfloat162(lo[0], lo[1]);
    hh = split2(v.z, v.w, lo);
    h[i * 2 + 1] = hh; l[i * 2 + 1] = __halves2bfloat162(lo[0], lo[1]);
}

// ---------------------------------------------------------------------------
// proj (fused Q/K/V via blockIdx.z): C = X·W^T + bias.
// X fp32 in-register split; W pre-split bf16 (uint2 loads, no split math).
// 4-buffer smem pipeline, __syncthreads every 2 K-chunks.
// ---------------------------------------------------------------------------
#define PJ_BUFE 3072
#define PJ_NBUF 4
#define PJ_ARRE (PJ_NBUF * PJ_BUFE)
#define PJ_SMEM (4 * PJ_ARRE * 2)
__global__ __launch_bounds__(256, 2) void proj_mma(
    const float* __restrict__ query, const float* __restrict__ key,
    const float* __restrict__ value,
    const bf16* __restrict__ Whs, const bf16* __restrict__ Wls,
    const float* __restrict__ bq, const float* __restrict__ bk,
    const float* __restrict__ bv,
    bf16* __restrict__ Qh, bf16* __restrict__ Ql,
    bf16* __restrict__ KSh, bf16* __restrict__ KSl,
    bf16* __restrict__ KCh, bf16* __restrict__ KCl,
    bf16* __restrict__ Vh, bf16* __restrict__ Vl)
{
    extern __shared__ bf16 sm[];
    bf16* Ah = sm;
    bf16* Al = sm + PJ_ARRE;
    bf16* Bh = sm + 2 * PJ_ARRE;
    bf16* Bl = sm + 3 * PJ_ARRE;

    const int zz = blockIdx.z;
    const float *X, *bias;
    bf16 *o0h, *o0l, *o1h = nullptr, *o1l = nullptr;
    int mode, do_relu;
    if (zz == 0)      { X = query; bias = bq; o0h = Qh;  o0l = Ql;  mode = 0; do_relu = 1; }
    else if (zz == 1) { X = key;   bias = bk; o0h = KSh; o0l = KSl; o1h = KCh; o1l = KCl; mode = 1; do_relu = 1; }
    else              { X = value; bias = bv; o0h = Vh;  o0l = Vl;  mode = 0; do_relu = 0; }
    const bf16* Whp = Whs + (size_t)zz * EE;
    const bf16* Wlp = Wls + (size_t)zz * EE;

    const int tid = threadIdx.x, lane = tid & 31, warp = tid >> 5;
    const int wy = warp >> 2, wx = warp & 3;
    const int m0 = blockIdx.y * 128, n0 = blockIdx.x * 128;
    const int lr = tid >> 2, lc = tid & 3;

    uint32_t aA[4], aB[4];
    {
        int ar = lane & 15, ac = (lane >> 4) << 3;
#pragma unroll
        for (int mi = 0; mi < 4; mi++)
            aA[mi] = sptr(&Ah[(wy * 64 + mi * 16 + ar) * 24 + ac]);
        int br = lane & 7, bc = ((lane >> 3) & 1) << 3;
#pragma unroll
        for (int ni = 0; ni < 4; ni++)
            aB[ni] = sptr(&Bh[(wx * 32 + ni * 8 + br) * 24 + bc]);
    }
    const uint32_t dHL = (uint32_t)PJ_ARRE * 2;
    const uint32_t dBUF = (uint32_t)PJ_BUFE * 2;

    float4 xa[2];
    uint2 wh[2], wl[2];
    auto gload = [&](int k0) {
#pragma unroll
        for (int it = 0; it < 2; it++) {
            xa[it] = *(const float4*)&X[(size_t)(m0 + lr + it * 64) * E_DIM + k0 + lc * 4];
            size_t wo = (size_t)(n0 + lr + it * 64) * E_DIM + k0 + lc * 4;
            wh[it] = *(const uint2*)&Whp[wo];
            wl[it] = *(const uint2*)&Wlp[wo];
        }
    };
    auto sstore = [&](int buf) {
#pragma unroll
        for (int it = 0; it < 2; it++) {
            int row = lr + it * 64;
            int off = buf * PJ_BUFE + row * 24 + lc * 4;
            bf16 lo[2];
            bf162 hh = split2(xa[it].x, xa[it].y, lo);
            *(bf162*)&Ah[off]     = hh; *(bf162*)&Al[off]     = __halves2bfloat162(lo[0], lo[1]);
            hh = split2(xa[it].z, xa[it].w, lo);
            *(bf162*)&Ah[off + 2] = hh; *(bf162*)&Al[off + 2] = __halves2bfloat162(lo[0], lo[1]);
            *(uint2*)&Bh[off] = wh[it];
            *(uint2*)&Bl[off] = wl[it];
        }
    };

    float cacc[4][4][4];
#pragma unroll
    for (int i = 0; i < 4; i++)
#pragma unroll
        for (int j = 0; j < 4; j++)
#pragma unroll
            for (int k = 0; k < 4; k++) cacc[i][j][k] = 0.f;

    const int NIT = E_DIM / 16;
    gload(0);  sstore(0);
    gload(16); sstore(1);
    gload(32);
    __syncthreads();
    for (int i = 0; i < NIT; i++) {
        if (i + 2 < NIT) {
            sstore((i + 2) & 3);
            if (i + 3 < NIT) gload((i + 3) * 16);
        }
        uint32_t bo = (i & 3) * dBUF;
        uint32_t ah[4][4], al[4][4], bh[4][2], bl[4][2];
#pragma unroll
        for (int mi = 0; mi < 4; mi++) { ldm_x4(ah[mi], aA[mi] + bo); ldm_x4(al[mi], aA[mi] + bo + dHL); }
#pragma unroll
        for (int ni = 0; ni < 4; ni++) { ldm_x2(bh[ni], aB[ni] + bo); ldm_x2(bl[ni], aB[ni] + bo + dHL); }
        MMA_BLOCK(ah, bh); MMA_BLOCK(ah, bl); MMA_BLOCK(al, bh);
        if (i & 1) __syncthreads();
    }

    const int gid = lane >> 2, tig = lane & 3;
#pragma unroll
    for (int mi = 0; mi < 4; mi++)
#pragma unroll
        for (int ni = 0; ni < 4; ni++) {
            int col = n0 + wx * 32 + ni * 8 + tig * 2;
            float b0v = bias[col], b1v = bias[col + 1];
#pragma unroll
            for (int half = 0; half < 2; half++) {
                int m = m0 + wy * 64 + mi * 16 + gid + half * 8;
                int bb = m & (B_DIM - 1);
                int t = m >> 2;
                float c0 = cacc[mi][ni][half * 2] + b0v;
                float c1 = cacc[mi][ni][half * 2 + 1] + b1v;
                if (do_relu) { c0 = fmaxf(c0, 0.f); c1 = fmaxf(c1, 0.f); }
                size_t o = ((size_t)bb * L_DIM + t) * E_DIM + col;
                bf16 lo[2];
                if (mode == 1) {
                    float th = PIO2 * (float)(t + 1) * INV_M;
                    float sn = __sinf(th), cs = __cosf(th);
                    bf162 hh = split2(sn * c0, sn * c1, lo);
                    *(bf162*)&o0h[o] = hh; *(bf162*)&o0l[o] = __halves2bfloat162(lo[0], lo[1]);
                    hh = split2(cs * c0, cs * c1, lo);
                    *(bf162*)&o1h[o] = hh; *(bf162*)&o1l[o] = __halves2bfloat162(lo[0], lo[1]);
                } else {
                    bf162 hh = split2(c0, c1, lo);
                    *(bf162*)&o0h[o] = hh; *(bf162*)&o0l[o] = __halves2bfloat162(lo[0], lo[1]);
                }
            }
        }
}

// ---------------------------------------------------------------------------
// kv: KV[b,d,m] = sum_s ksel[b,s,d] * v[b,s,m]. cp.async 3-stage, BK=32.
// ---------------------------------------------------------------------------
#define K_STAGE 34816
#define K_SMEM  (3 * K_STAGE)
__global__ __launch_bounds__(256) void kv_mma(
    const bf16* __restrict__ ksh, const bf16* __restrict__ ksl,
    const bf16* __restrict__ kch, const bf16* __restrict__ kcl,
    const bf16* __restrict__ vh,  const bf16* __restrict__ vl,
    bf16* __restrict__ kvh, bf16* __restrict__ kvl)
{
    extern __shared__ bf16 sm[];
    const int tid = threadIdx.x, lane = tid & 31, warp = tid >> 5;
    const int wy = warp >> 2, wx = warp & 3;
    const int b = blockIdx.z, d0 = blockIdx.y * 128, m0 = blockIdx.x * 128;
    const uint32_t smb = sptr(sm);

    const bf16 *Ahg, *Alg;
    int dbase;
    if (d0 < E_DIM) { Ahg = ksh; Alg = ksl; dbase = d0; }
    else            { Ahg = kch; Alg = kcl; dbase = d0 - E_DIM; }
    Ahg += (size_t)b * S_DIM * E_DIM; Alg += (size_t)b * S_DIM * E_DIM;
    const bf16* Vhg = vh + (size_t)b * S_DIM * E_DIM;
    const bf16* Vlg = vl + (size_t)b * S_DIM * E_DIM;

    uint32_t aA[4], aB[4];
    {
        int ar = (lane & 7) + ((lane >> 4) << 3);
        int ac = ((lane >> 3) & 1) << 3;
#pragma unroll
        for (int mi = 0; mi < 4; mi++)
            aA[mi] = smb + (ar * 136 + wy * 64 + mi * 16 + ac) * 2;
        int br = lane & 15;
#pragma unroll
        for (int ni = 0; ni < 4; ni++)
            aB[ni] = smb + 17408 + (br * 136 + wx * 32 + ni * 8) * 2;
    }

    auto load_stage = [&](int st, int s0) {
        uint32_t base = smb + st * K_STAGE;
#pragma unroll
        for (int u = 0; u < 2; u++) {
            int id = tid + u * 256;
            int row = id >> 4, seg = id & 15;
            uint32_t da = base + (row * 136 + seg * 8) * 2;
            size_t ga = (size_t)(s0 + row) * E_DIM + dbase + seg * 8;
            cp16(da, Ahg + ga); cp16(da + 8704, Alg + ga);
            size_t gb = (size_t)(s0 + row) * E_DIM + m0 + seg * 8;
            cp16(da + 17408, Vhg + gb); cp16(da + 26112, Vlg + gb);
        }
    };

    float cacc[4][4][4];
#pragma unroll
    for (int i = 0; i < 4; i++)
#pragma unroll
        for (int j = 0; j < 4; j++)
#pragma unroll
            for (int k = 0; k < 4; k++) cacc[i][j][k] = 0.f;

    load_stage(0, 0);  CP_COMMIT;
    load_stage(1, 32); CP_COMMIT;
    int buf = 0;
    for (int s0 = 0; s0 < S_DIM; s0 += 32) {
        CP_WAIT1; __syncthreads();
        if (s0 + 64 < S_DIM) {
            int nst = buf + 2; if (nst >= 3) nst -= 3;
            load_stage(nst, s0 + 64);
        }
        CP_COMMIT;
        uint32_t soff = buf * K_STAGE;
#pragma unroll
        for (int kk = 0; kk < 32; kk += 16) {
            uint32_t ko = soff + kk * 272;
            uint32_t ah[4][4], al[4][4], bh[4][2], bl[4][2];
#pragma unroll
            for (int mi = 0; mi < 4; mi++) { ldm_x4t(ah[mi], aA[mi] + ko); ldm_x4t(al[mi], aA[mi] + ko + 8704); }
#pragma unroll
            for (int ni = 0; ni < 4; ni++) { ldm_x2t(bh[ni], aB[ni] + ko); ldm_x2t(bl[ni], aB[ni] + ko + 8704); }
            MMA_BLOCK(ah, bh); MMA_BLOCK(ah, bl); MMA_BLOCK(al, bh);
        }
        buf++; if (buf == 3) buf = 0;
    }

    const int gid = lane >> 2, tig = lane & 3;
#pragma unroll
    for (int mi = 0; mi < 4; mi++)
#pragma unroll
        for (int ni = 0; ni < 4; ni++) {
            int col = m0 + wx * 32 + ni * 8 + tig * 2;
#pragma unroll
            for (int half = 0; half < 2; half++) {
                int d = d0 + wy * 64 + mi * 16 + gid + half * 8;
                size_t o = ((size_t)b * D2 + d) * E_DIM + col;
                bf16 lo[2];
                bf162 hh = split2(cacc[mi][ni][half * 2], cacc[mi][ni][half * 2 + 1], lo);
                *(bf162*)&kvh[o] = hh;
                *(bf162*)&kvl[o] = __halves2bfloat162(lo[0], lo[1]);
            }
        }
}

// ---------------------------------------------------------------------------
// attn (dual): Y1 = Q@KVs, Y2 = Q@KVc; out = Z·(sin_l·Y1 + cos_l·Y2).
// Tile M=128 N=64 BK=32; warps 2x4; 2-stage double buffer, 2 CTAs/SM.
// Stage bytes: Ah 0, Al 10240, B1h 20480, B1l 25088, B2h 29696, B2l 34304.
// ---------------------------------------------------------------------------
#define AT_STAGEE 19456
#define AT_STAGE  (AT_STAGEE * 2)
#define AT_SMEM   (2 * AT_STAGE)
__global__ __launch_bounds__(256, 2) void attn_dual(
    const bf16* __restrict__ qh, const bf16* __restrict__ ql,
    const bf16* __restrict__ kvh, const bf16* __restrict__ kvl,
    float* __restrict__ out)
{
    extern __shared__ bf16 sm[];
    const int tid = threadIdx.x, lane = tid & 31, warp = tid >> 5;
    const int wy = warp >> 2, wx = warp & 3;   // wy 0..1, wx 0..3
    const int b = blockIdx.z, l0 = blockIdx.y * 128, m0 = blockIdx.x * 64;
    const uint32_t smb = sptr(sm);

    const bf16* Qh = qh + (size_t)b * L_DIM * E_DIM;
    const bf16* Ql = ql + (size_t)b * L_DIM * E_DIM;
    const bf16* KVh = kvh + (size_t)b * D2 * E_DIM;
    const bf16* KVl = kvl + (size_t)b * D2 * E_DIM;

    uint32_t aA[4], aB[2];
    {
        int ar = lane & 15, ac = (lane >> 4) << 3;
#pragma unroll
        for (int mi = 0; mi < 4; mi++)
            aA[mi] = smb + ((wy * 64 + mi * 16 + ar) * 40 + ac) * 2;
        int br = lane & 15;
#pragma unroll
        for (int ni = 0; ni < 2; ni++)
            aB[ni] = smb + (10240 + (br * 72 + wx * 16 + ni * 8)) * 2;
    }

    auto load_stage = [&](int st, int k0) {
        uint32_t base = smb + st * AT_STAGE;
        // A: 128x32 hi/lo
#pragma unroll
        for (int u = 0; u < 2; u++) {
            int id = tid + u * 256;
            int row = id >> 2, seg = id & 3;
            uint32_t da = base + (row * 40 + seg * 8) * 2;
            size_t ga = (size_t)(l0 + row) * E_DIM + k0 + seg * 8;
            cp16(da, Qh + ga); cp16(da + 10240, Ql + ga);
        }
        // B1 (KVs rows k0..), B2 (KVc rows E+k0..): each 32x64 hi/lo
        {
            int row = tid >> 3, seg = tid & 7;
            uint32_t db = base + 20480 + (row * 72 + seg * 8) * 2;
            size_t g1 = (size_t)(k0 + row) * E_DIM + m0 + seg * 8;
            size_t g2 = (size_t)(E_DIM + k0 + row) * E_DIM + m0 + seg * 8;
            cp16(db, KVh + g1);         cp16(db + 4608, KVl + g1);
            cp16(db + 9216, KVh + g2);  cp16(db + 13824, KVl + g2);
        }
    };

    float cacc[2][4][2][4];
#pragma unroll
    for (int s = 0; s < 2; s++)
#pragma unroll
        for (int i = 0; i < 4; i++)
#pragma unroll
            for (int j = 0; j < 2; j++)
#pragma unroll
                for (int k = 0; k < 4; k++) cacc[s][i][j][k] = 0.f;

    load_stage(0, 0); CP_COMMIT;
    int buf = 0;
    for (int k0 = 0; k0 < E_DIM; k0 += 32) {
        CP_WAIT0; __syncthreads();
        if (k0 + 32 < E_DIM) load_stage(buf ^ 1, k0 + 32);
        CP_COMMIT;
        uint32_t soff = buf * AT_STAGE;
#pragma unroll
        for (int kk = 0; kk < 32; kk += 16) {
            uint32_t koA = soff + kk * 2;
            uint32_t koB = soff + kk * 144;   // 72 elems * 2B per row
            uint32_t ah[4][4], al[4][4];
#pragma unroll
            for (int mi = 0; mi < 4; mi++) { ldm_x4(ah[mi], aA[mi] + koA); ldm_x4(al[mi], aA[mi] + koA + 10240); }
#pragma unroll
            for (int mat = 0; mat < 2; mat++) {
                uint32_t mo = koB + mat * 9216;
                uint32_t bh[2][2], bl[2][2];
#pragma unroll
                for (int ni = 0; ni < 2; ni++) { ldm_x2t(bh[ni], aB[ni] + mo); ldm_x2t(bl[ni], aB[ni] + mo + 4608); }
#pragma unroll
                for (int mi = 0; mi < 4; mi++)
#pragma unroll
                    for (int ni = 0; ni < 2; ni++) {
                        mma16816(cacc[mat][mi][ni], ah[mi], bh[ni]);
                        mma16816(cacc[mat][mi][ni], ah[mi], bl[ni]);
                        mma16816(cacc[mat][mi][ni], al[mi], bh[ni]);
                    }
            }
        }
        buf ^= 1;
    }

    const int gid = lane >> 2, tig = lane & 3;
#pragma unroll
    for (int mi = 0; mi < 4; mi++)
#pragma unroll
        for (int half = 0; half < 2; half++) {
            int l = l0 + wy * 64 + mi * 16 + gid + half * 8;
            float th = PIO2 * (float)(l + 1) * INV_M;
            float sn = __sinf(th), cs = __cosf(th);
            float zv = g_Z[b * L_DIM + l];
#pragma unroll
            for (int ni = 0; ni < 2; ni++) {
                int col = m0 + wx * 16 + ni * 8 + tig * 2;
                float v0 = zv * (sn * cacc[0][mi][ni][half * 2]     + cs * cacc[1][mi][ni][half * 2]);
                float v1 = zv * (sn * cacc[0][mi][ni][half * 2 + 1] + cs * cacc[1][mi][ni][half * 2 + 1]);
                *(float2*)&out[((size_t)l * B_DIM + b) * E_DIM + col] = make_float2(v0, v1);
            }
        }
}

// ---------------------------------------------------------------------------
// ksum (hi-only) + z (warp-per-row)
// ---------------------------------------------------------------------------
__global__ void ksum_part_kernel()
{
    const int f = blockIdx.x * 256 + threadIdx.x;
    const int b = blockIdx.y;
    const int chunk = blockIdx.z;
    const int s0 = chunk * (S_DIM / NCHUNK);
    float ss = 0.f, sc = 0.f;
#pragma unroll 4
    for (int i = 0; i < S_DIM / NCHUNK; i++) {
        size_t idx = ((size_t)b * S_DIM + s0 + i) * E_DIM + f;
        ss += __bfloat162float(g_KSh[idx]);
        sc += __bfloat162float(g_KCh[idx]);
    }
    g_KsumPartS[(chunk * B_DIM + b) * E_DIM + f] = ss;
    g_KsumPartC[(chunk * B_DIM + b) * E_DIM + f] = sc;
}

__global__ void ksum_reduce_kernel()
{
    int idx = blockIdx.x * 256 + threadIdx.x;
    if (idx >= B_DIM * E_DIM) return;
    float ss = 0.f, sc = 0.f;
#pragma unroll
    for (int c = 0; c < NCHUNK; c++) {
        ss += g_KsumPartS[c * B_DIM * E_DIM + idx];
        sc += g_KsumPartC[c * B_DIM * E_DIM + idx];
    }
    g_KsumS[idx] = ss;
    g_KsumC[idx] = sc;
}

__global__ void z_kernel()
{
    const int warp = threadIdx.x >> 5, lane = threadIdx.x & 31;
    const int l = blockIdx.x * 8 + warp;
    const int b = blockIdx.y;
    const size_t base = ((size_t)b * L_DIM + l) * E_DIM;
    const float th = PIO2 * (float)(l + 1) * INV_M;
    const float sl = __sinf(th), cl = __cosf(th);

    float acc = 0.f;
#pragma unroll 8
    for (int jj = 0; jj < 32; jj++) {
        int f = jj * 32 + lane;
        float q = __bfloat162float(g_Qh[base + f]);
        acc += q * (sl * g_KsumS[b * E_DIM + f] + cl * g_KsumC[b * E_DIM + f]);
    }
#pragma unroll
    for (int off = 16; off > 0; off >>= 1)
        acc += __shfl_down_sync(0xFFFFFFFFu, acc, off);
    if (lane == 0)
        g_Z[b * L_DIM + l] = 1.f / fmaxf(acc, EPS_F);
}

// ---------------------------------------------------------------------------
// Launch
// ---------------------------------------------------------------------------
extern "C" void kernel_launch(void* const* d_in, const int* in_sizes, int n_in,
                              void* d_out, int out_size)
{
    const float* query = (const float*)d_in[0];
    const float* key   = (const float*)d_in[1];
    const float* value = (const float*)d_in[2];
    const float* Wq    = (const float*)d_in[3];
    const float* bq    = (const float*)d_in[4];
    const float* Wk    = (const float*)d_in[5];
    const float* bk    = (const float*)d_in[6];
    const float* Wv    = (const float*)d_in[7];
    const float* bv    = (const float*)d_in[8];
    float* out = (float*)d_out;

    cudaFuncSetAttribute(proj_mma,  cudaFuncAttributeMaxDynamicSharedMemorySize, PJ_SMEM);
    cudaFuncSetAttribute(kv_mma,    cudaFuncAttributeMaxDynamicSharedMemorySize, K_SMEM);
    cudaFuncSetAttribute(attn_dual, cudaFuncAttributeMaxDynamicSharedMemorySize, AT_SMEM);

    bf16 *Qh, *Ql, *KSh, *KSl, *KCh, *KCl, *Vh, *Vl, *KVh, *KVl, *Wh, *Wl;
    cudaGetSymbolAddress((void**)&Qh, g_Qh);   cudaGetSymbolAddress((void**)&Ql, g_Ql);
    cudaGetSymbolAddress((void**)&KSh, g_KSh); cudaGetSymbolAddress((void**)&KSl, g_KSl);
    cudaGetSymbolAddress((void**)&KCh, g_KCh); cudaGetSymbolAddress((void**)&KCl, g_KCl);
    cudaGetSymbolAddress((void**)&Vh, g_Vh);   cudaGetSymbolAddress((void**)&Vl, g_Vl);
    cudaGetSymbolAddress((void**)&KVh, g_KVh); cudaGetSymbolAddress((void**)&KVl, g_KVl);
    cudaGetSymbolAddress((void**)&Wh, g_Wh);   cudaGetSymbolAddress((void**)&Wl, g_Wl);

    // weight pre-split (12 MB total, once per call)
    const int n4w = EE / 4;
    split_w_kernel<<<n4w / 256, 256>>>((const float4*)Wq, (bf162*)Wh, (bf162*)Wl, n4w);
    split_w_kernel<<<n4w / 256, 256>>>((const float4*)Wk, (bf162*)(Wh + EE), (bf162*)(Wl + EE), n4w);
    split_w_kernel<<<n4w / 256, 256>>>((const float4*)Wv, (bf162*)(Wh + 2 * EE), (bf162*)(Wl + 2 * EE), n4w);

    dim3 gProj(E_DIM / 128, (L_DIM * B_DIM) / 128, 3);   // (8, 64, 3) fused Q/K/V
    proj_mma<<<gProj, 256, PJ_SMEM>>>(query, key, value, Wh, Wl, bq, bk, bv,
                                      Qh, Ql, KSh, KSl, KCh, KCl, Vh, Vl);

    dim3 gKV(E_DIM / 128, D2 / 128, B_DIM);           // (8, 16, 4)
    kv_mma<<<gKV, 256, K_SMEM>>>(KSh, KSl, KCh, KCl, Vh, Vl, KVh, KVl);

    dim3 gKsum(E_DIM / 256, B_DIM, NCHUNK);
    ksum_part_kernel<<<gKsum, 256>>>();
    ksum_reduce_kernel<<<(B_DIM * E_DIM + 255) / 256, 256>>>();
    dim3 gZ(L_DIM / 8, B_DIM);
    z_kernel<<<gZ, 256>>>();

    dim3 gAttn(E_DIM / 64, L_DIM / 128, B_DIM);       // (16, 16, 4)
    attn_dual<<<gAttn, 256, AT_SMEM>>>(Qh, Ql, KVh, KVl, out);
}